// round 16
// baseline (speedup 1.0000x reference)
#include <cuda_runtime.h>
#include <cuda_fp16.h>
#include <cstdint>

#define B_  4
#define T_  2048
#define C_  768
#define H_  12
#define BH_ (B_*H_)
#define MT_ 8192

// fp16 slots, t-major per 32-k chunk: slot = chunk*8 + t*2 + ks,
// u2 = {h2(c,c+1), h2(c+8,c+9)}, c = chunk*32 + ks*16 + t*2. 192 u2 per row.
__device__ uint2 g_xh [MT_*192];     // x
__device__ uint2 g_oh [MT_*192];     // attention output (proj A)
__device__ uint2 g_wah[2304*192];    // W_attn^T slots
__device__ uint2 g_wph[768*192];     // W_proj^T slots
// fp16 attention operands
__device__ uint32_t g_q2[BH_*2048*32];
__device__ uint32_t g_k2[BH_*2048*32];
__device__ uint2    g_v2[BH_*32*64*16];

// ---------------------------------------------------------------------------
__device__ __forceinline__ uint32_t f2h2(float x, float y) {
    uint32_t r; asm("cvt.rn.f16x2.f32 %0, %1, %2;" : "=r"(r) : "f"(y), "f"(x));
    return r;
}
__device__ __forceinline__ uint32_t smem_u32(const void* p) {
    uint32_t a;
    asm("{ .reg .u64 t; cvta.to.shared.u64 t, %1; cvt.u32.u64 %0, t; }" : "=r"(a) : "l"(p));
    return a;
}
__device__ __forceinline__ void cpa16(uint32_t dst, const void* src) {
    asm volatile("cp.async.cg.shared.global [%0], [%1], 16;"
                 :: "r"(dst), "l"(__cvta_generic_to_global(src)));
}
__device__ __forceinline__ void cpa_commit() { asm volatile("cp.async.commit_group;"); }
template<int N> __device__ __forceinline__ void cpa_wait() {
    asm volatile("cp.async.wait_group %0;" :: "n"(N));
}
__device__ __forceinline__ void mma16h(float* d, const uint32_t* a, const uint32_t* b) {
    asm volatile("mma.sync.aligned.m16n8k16.row.col.f32.f16.f16.f32 "
        "{%0,%1,%2,%3}, {%4,%5,%6,%7}, {%8,%9}, {%0,%1,%2,%3};"
        : "+f"(d[0]), "+f"(d[1]), "+f"(d[2]), "+f"(d[3])
        : "r"(a[0]), "r"(a[1]), "r"(a[2]), "r"(a[3]), "r"(b[0]), "r"(b[1]));
}

// ---------------------------------------------------------------------------
// Pack kernels (t-major slot order)
// ---------------------------------------------------------------------------
__global__ __launch_bounds__(256) void pack_a(const float* __restrict__ src,
                                              uint2* __restrict__ dst)
{
    int idx = blockIdx.x * 256 + threadIdx.x;   // MT_*192
    int r = idx / 192, s = idx - r * 192;
    int chunk = s >> 3, rem = s & 7;
    int t = rem >> 1, kl = rem & 1;
    int c = chunk * 32 + kl * 16 + t * 2;
    const float* p = src + (size_t)r * C_ + c;
    dst[idx] = make_uint2(f2h2(p[0], p[1]), f2h2(p[8], p[9]));
}

// Both weight matrices in one launch: blocks [0,72) -> W_attn, [72,96) -> W_proj
__global__ __launch_bounds__(256) void pack_b2(const float* __restrict__ Wa,
                                               const float* __restrict__ Wp,
                                               uint2* __restrict__ da,
                                               uint2* __restrict__ dp)
{
    __shared__ float sw[32][33];
    int bx = blockIdx.x;
    const float* W; uint2* dst; int N;
    if (bx < 72) { W = Wa; dst = da; N = 2304; }
    else         { W = Wp; dst = dp; N = 768; bx -= 72; }
    const int n0 = bx * 32;
    const int kk = threadIdx.x >> 5, nn = threadIdx.x & 31;
    const int nl = threadIdx.x >> 3, s = threadIdx.x & 7;
    const int t = s >> 1, kl = s & 1;
    const int kb = kl * 16 + t * 2;
    for (int kc = 0; kc < 24; kc++) {
        __syncthreads();
#pragma unroll
        for (int p = 0; p < 4; p++)
            sw[kk + p * 8][nn] = W[(size_t)(kc * 32 + kk + p * 8) * N + n0 + nn];
        __syncthreads();
        dst[(size_t)(n0 + nl) * 192 + kc * 8 + s] =
            make_uint2(f2h2(sw[kb][nl], sw[kb + 1][nl]),
                       f2h2(sw[kb + 8][nl], sw[kb + 9][nl]));
    }
}

// ---------------------------------------------------------------------------
// GEMM (pure fp16, paired-ks fragments). CTA 128m x 128n, 4 warps (2m x 2n),
// warp tile m64n64 -> 64 MMAs per 16 LDS.128 per chunk (ratio 4).
// 3-stage cp.async, dense 64B rows. Stage 16KB; smem 68KB (V transpose).
// ---------------------------------------------------------------------------
#define GSTAGE 1024
#define GEMM_SMEM 69632

template<int MODE>
__global__ __launch_bounds__(128, 2) void gemm_tc(const uint4* __restrict__ Ap,
                                                  const uint4* __restrict__ Bp,
                                                  const float* __restrict__ bias,
                                                  float* __restrict__ out)
{
    extern __shared__ uint4 sm4[];
    const uint32_t smb = smem_u32(sm4);
    const int tid = threadIdx.x, w = tid >> 5, lane = tid & 31, g = lane >> 2, t = lane & 3;
    const int M0 = blockIdx.y * 128, N0 = blockIdx.x * 128;
    const int mw = (w & 1) * 64, nw = (w >> 1) * 64;

    // Loaders: 128 threads, each owns one row of A and one row of B (4 u4 each)
    const uint4* aBase = Ap + (size_t)(M0 + tid) * 96;
    const uint4* bBase = Bp + (size_t)(N0 + tid) * 96;
    const uint32_t dA0 = smb + (uint32_t)(tid * 4) * 16;
    const uint32_t dB0 = smb + (uint32_t)(512 + tid * 4) * 16;

    float acc[4][8][4];
#pragma unroll
    for (int mt = 0; mt < 4; mt++)
#pragma unroll
        for (int nt = 0; nt < 8; nt++)
#pragma unroll
            for (int r = 0; r < 4; r++) acc[mt][nt][r] = 0.f;

    auto issue = [&](int c, int buf) {
        uint32_t o = (uint32_t)buf * GSTAGE * 16u;
#pragma unroll
        for (int i = 0; i < 4; i++) {
            cpa16(dA0 + o + i * 16u, aBase + c * 4 + i);
            cpa16(dB0 + o + i * 16u, bBase + c * 4 + i);
        }
        cpa_commit();
    };

    issue(0, 0);
    issue(1, 1);

#pragma unroll 1
    for (int c3 = 0; c3 < 8; c3++) {
#pragma unroll
        for (int sub = 0; sub < 3; sub++) {
            const int c = c3 * 3 + sub;
            if (c < 23) cpa_wait<1>(); else cpa_wait<0>();
            __syncthreads();
            if (c < 22) issue(c + 2, (sub + 2) % 3);
            const uint4* sA = sm4 + sub * GSTAGE;
            const uint4* sB = sA + 512;

            // A fragments for both k-steps: 8 LDS.128 -> 4 mt x 2 ks
            uint32_t ah0[4][4], ah1[4][4];
#pragma unroll
            for (int mt = 0; mt < 4; mt++) {
                uint4 u0 = sA[(mw + mt * 16 + g) * 4 + t];
                uint4 u1 = sA[(mw + mt * 16 + g + 8) * 4 + t];
                ah0[mt][0] = u0.x; ah0[mt][1] = u1.x; ah0[mt][2] = u0.y; ah0[mt][3] = u1.y;
                ah1[mt][0] = u0.z; ah1[mt][1] = u1.z; ah1[mt][2] = u0.w; ah1[mt][3] = u1.w;
            }
            // B: one LDS.128 per nt feeds 8 MMAs
#pragma unroll
            for (int nt = 0; nt < 8; nt++) {
                uint4 ub = sB[(nw + nt * 8 + g) * 4 + t];
                uint32_t b0[2] = { ub.x, ub.y };
                uint32_t b1[2] = { ub.z, ub.w };
#pragma unroll
                for (int mt = 0; mt < 4; mt++) mma16h(acc[mt][nt], ah0[mt], b0);
#pragma unroll
                for (int mt = 0; mt < 4; mt++) mma16h(acc[mt][nt], ah1[mt], b1);
            }
        }
    }

    if (MODE == 1) {
#pragma unroll
        for (int mt = 0; mt < 4; mt++)
#pragma unroll
            for (int nt = 0; nt < 8; nt++)
#pragma unroll
                for (int rr = 0; rr < 2; rr++) {
                    int m_g = M0 + mw + mt * 16 + g + rr * 8;
                    int n_g = N0 + nw + nt * 8 + 2 * t;
                    float2 v = { acc[mt][nt][2 * rr] + bias[n_g],
                                 acc[mt][nt][2 * rr + 1] + bias[n_g + 1] };
                    *reinterpret_cast<float2*>(out + (size_t)m_g * C_ + n_g) = v;
                }
        return;
    }

    const int which = N0 / C_;   // 128-wide tile never straddles q/k/v
    if (which < 2) {
        uint32_t* dstp = which ? g_k2 : g_q2;
        const float scl = which ? 1.f : 0.125f;
#pragma unroll
        for (int mt = 0; mt < 4; mt++)
#pragma unroll
            for (int nt = 0; nt < 8; nt++)
#pragma unroll
                for (int rr = 0; rr < 2; rr++) {
                    int m_g = M0 + mw + mt * 16 + g + rr * 8;
                    int n_g = N0 + nw + nt * 8 + 2 * t;
                    float v0 = (acc[mt][nt][2 * rr] + bias[n_g]) * scl;
                    float v1 = (acc[mt][nt][2 * rr + 1] + bias[n_g + 1]) * scl;
                    int cc = n_g - which * C_;
                    int h = cc >> 6, d = cc & 63;
                    int b = m_g >> 11, tok = m_g & 2047;
                    int idx = 8 * ((d >> 1) & 3) + 2 * (d >> 4) + ((d >> 3) & 1);
                    dstp[((size_t)(b * H_ + h) * 2048 + tok) * 32 + idx] = f2h2(v0, v1);
                }
    } else {
        // V: two heads per 128-wide tile; transpose via smem [128][133] floats
        __syncthreads();
        float* sv = reinterpret_cast<float*>(sm4);
#pragma unroll
        for (int mt = 0; mt < 4; mt++)
#pragma unroll
            for (int nt = 0; nt < 8; nt++)
#pragma unroll
                for (int rr = 0; rr < 2; rr++) {
                    int row = mw + mt * 16 + g + rr * 8;
                    int col = nw + nt * 8 + 2 * t;
                    sv[row * 133 + col]     = acc[mt][nt][2 * rr] + bias[N0 + col];
                    sv[row * 133 + col + 1] = acc[mt][nt][2 * rr + 1] + bias[N0 + col + 1];
                }
        __syncthreads();
        const int b = M0 >> 11, tok0 = M0 & 2047;
        const int h0 = (N0 - 2 * C_) >> 6;
#pragma unroll
        for (int r = 0; r < 32; r++) {
            int id = tid + 128 * r;            // 4096 slots: 2kb x 128c x 16
            int kb_l = id >> 11, rem = id & 2047;
            int cloc = rem >> 4, sidx = rem & 15;
            int tt = sidx >> 2, ks = sidx & 3;
            int tl0 = kb_l * 64 + ks * 16 + 2 * tt;
            float a   = sv[tl0 * 133 + cloc];
            float bb  = sv[(tl0 + 1) * 133 + cloc];
            float cfl = sv[(tl0 + 8) * 133 + cloc];
            float dfl = sv[(tl0 + 9) * 133 + cloc];
            int h = h0 + (cloc >> 6), d = cloc & 63;
            int kbg = (tok0 >> 6) + kb_l;
            g_v2[(((size_t)(b * H_ + h) * 32 + kbg) * 64 + d) * 16 + sidx] =
                make_uint2(f2h2(a, bb), f2h2(cfl, dfl));
        }
    }
}

// ---------------------------------------------------------------------------
// Flash attention, fp16 single-term (unchanged from R15)
// ---------------------------------------------------------------------------
#define ATT_SMEM (4608*16)

__global__ __launch_bounds__(256, 2) void attn_tc()
{
    extern __shared__ uint4 sm4[];
    const uint32_t smb = smem_u32(sm4);
    const int bh = blockIdx.y;
    const int qb = (gridDim.x - 1) - blockIdx.x;
    const int tid = threadIdx.x, w = tid >> 5, lane = tid & 31, g = lane >> 2, t = lane & 3;
    const int m0 = w * 16;

    {
        const int qr = tid >> 1, qs = (tid & 1) * 4;
        const uint4* qBase = reinterpret_cast<const uint4*>(g_q2)
                           + ((size_t)bh * 2048 + qb * 128 + qr) * 8 + qs;
        const uint32_t dQ = smb + (uint32_t)(qr * 9 + qs) * 16;
#pragma unroll
        for (int j = 0; j < 4; j++) cpa16(dQ + j * 16u, qBase + j);
    }
    const int i_n = tid >> 2, i_s = tid & 3;
    const uint4* kBase = reinterpret_cast<const uint4*>(g_k2)
                       + ((size_t)bh * 2048 + i_n) * 8 + i_s;
    const uint4* vBase = reinterpret_cast<const uint4*>(g_v2)
                       + (size_t)bh * 32 * 512 + i_n * 8 + i_s;
    const uint32_t dK0 = smb + (uint32_t)(1152 + i_n * 9 + i_s) * 16;

    auto issueKV = [&](int kb, int buf) {
        uint32_t o = (uint32_t)buf * 1152u * 16u;
        cpa16(dK0 + o,           kBase + kb * 512);
        cpa16(dK0 + o + 64,      kBase + kb * 512 + 4);
        cpa16(dK0 + o + 576u*16, vBase + kb * 512);
        cpa16(dK0 + o + 576u*16 + 64, vBase + kb * 512 + 4);
        cpa_commit();
    };

    const int nkb = 2 * qb + 2;
    issueKV(0, 0);
    issueKV(1, 1);

    float o[8][4];
#pragma unroll
    for (int nt = 0; nt < 8; nt++)
#pragma unroll
        for (int r = 0; r < 4; r++) o[nt][r] = 0.f;
    float mrow[2] = { -1e30f, -1e30f }, lrow[2] = { 0.f, 0.f };

    const int aW = (m0 + g) * 9 + 2 * t;
    const int qr0 = qb * 128 + m0 + g;

    int cbuf = 0, ibuf = 2;
    for (int kb = 0; kb < nkb; kb++) {
        if (kb < nkb - 1) cpa_wait<1>(); else cpa_wait<0>();
        __syncthreads();
        if (kb + 2 < nkb) issueKV(kb + 2, ibuf);
        const uint4* sK = sm4 + 1152 + cbuf * 1152;
        const uint4* sV = sK + 576;

        float s[8][4];
#pragma unroll
        for (int nt = 0; nt < 8; nt++)
#pragma unroll
            for (int r = 0; r < 4; r++) s[nt][r] = 0.f;
#pragma unroll
        for (int kp = 0; kp < 2; kp++) {
            uint4 u0 = sm4[aW + kp];
            uint4 u1 = sm4[aW + 72 + kp];
            uint32_t a0[4] = { u0.x, u1.x, u0.y, u1.y };
            uint32_t a1[4] = { u0.z, u1.z, u0.w, u1.w };
            uint4 ub[8];
#pragma unroll
            for (int nt = 0; nt < 8; nt++)
                ub[nt] = sK[(nt * 8 + g) * 9 + 2 * t + kp];
#pragma unroll
            for (int nt = 0; nt < 8; nt++) {
                uint32_t b0[2] = { ub[nt].x, ub[nt].y };
                mma16h(s[nt], a0, b0);
            }
#pragma unroll
            for (int nt = 0; nt < 8; nt++) {
                uint32_t b1[2] = { ub[nt].z, ub[nt].w };
                mma16h(s[nt], a1, b1);
            }
        }

        if (kb >= 2 * qb) {
#pragma unroll
            for (int nt = 0; nt < 8; nt++) {
                int col = kb * 64 + nt * 8 + 2 * t;
                if (col > qr0)         s[nt][0] = -1e30f;
                if (col + 1 > qr0)     s[nt][1] = -1e30f;
                if (col > qr0 + 8)     s[nt][2] = -1e30f;
                if (col + 1 > qr0 + 8) s[nt][3] = -1e30f;
            }
        }

        float pm0 = -1e30f, pm1 = -1e30f;
#pragma unroll
        for (int nt = 0; nt < 8; nt++) {
            pm0 = fmaxf(pm0, fmaxf(s[nt][0], s[nt][1]));
            pm1 = fmaxf(pm1, fmaxf(s[nt][2], s[nt][3]));
        }
        pm0 = fmaxf(pm0, __shfl_xor_sync(0xffffffffu, pm0, 1));
        pm0 = fmaxf(pm0, __shfl_xor_sync(0xffffffffu, pm0, 2));
        pm1 = fmaxf(pm1, __shfl_xor_sync(0xffffffffu, pm1, 1));
        pm1 = fmaxf(pm1, __shfl_xor_sync(0xffffffffu, pm1, 2));
        float mn0 = fmaxf(mrow[0], pm0), mn1 = fmaxf(mrow[1], pm1);
        float al0 = __expf(mrow[0] - mn0), al1 = __expf(mrow[1] - mn1);
        mrow[0] = mn0; mrow[1] = mn1;
        float sum0 = 0.f, sum1 = 0.f;
#pragma unroll
        for (int nt = 0; nt < 8; nt++) {
            s[nt][0] = __expf(s[nt][0] - mn0); sum0 += s[nt][0];
            s[nt][1] = __expf(s[nt][1] - mn0); sum0 += s[nt][1];
            s[nt][2] = __expf(s[nt][2] - mn1); sum1 += s[nt][2];
            s[nt][3] = __expf(s[nt][3] - mn1); sum1 += s[nt][3];
        }
        sum0 += __shfl_xor_sync(0xffffffffu, sum0, 1);
        sum0 += __shfl_xor_sync(0xffffffffu, sum0, 2);
        sum1 += __shfl_xor_sync(0xffffffffu, sum1, 1);
        sum1 += __shfl_xor_sync(0xffffffffu, sum1, 2);
        lrow[0] = lrow[0] * al0 + sum0;
        lrow[1] = lrow[1] * al1 + sum1;
#pragma unroll
        for (int nt = 0; nt < 8; nt++) {
            o[nt][0] *= al0; o[nt][1] *= al0;
            o[nt][2] *= al1; o[nt][3] *= al1;
        }

#pragma unroll
        for (int kp = 0; kp < 2; kp++) {
            uint4 ub[8];
#pragma unroll
            for (int nt = 0; nt < 8; nt++)
                ub[nt] = sV[(nt * 8 + g) * 9 + 2 * t + kp];
#pragma unroll
            for (int half = 0; half < 2; half++) {
                const int ks = 2 * kp + half;
                uint32_t pa[4] = {
                    f2h2(s[2 * ks][0],     s[2 * ks][1]),
                    f2h2(s[2 * ks][2],     s[2 * ks][3]),
                    f2h2(s[2 * ks + 1][0], s[2 * ks + 1][1]),
                    f2h2(s[2 * ks + 1][2], s[2 * ks + 1][3]) };
#pragma unroll
                for (int nt = 0; nt < 8; nt++) {
                    uint32_t bv[2] = { half ? ub[nt].z : ub[nt].x,
                                       half ? ub[nt].w : ub[nt].y };
                    mma16h(o[nt], pa, bv);
                }
            }
        }
        cbuf = (cbuf == 2) ? 0 : cbuf + 1;
        ibuf = (ibuf == 2) ? 0 : ibuf + 1;
    }

    // epilogue: normalize, write fp16 A-slots for proj (t-major chunk order)
    float inv0 = 1.f / lrow[0], inv1 = 1.f / lrow[1];
    const int bI = bh / H_, hI = bh - bI * H_;
#pragma unroll
    for (int np = 0; np < 4; np++) {
        const int nt = np * 2;
        const int K16 = hI * 4 + np;
        const int slot = (K16 >> 1) * 8 + t * 2 + (K16 & 1);
#pragma unroll
        for (int rr = 0; rr < 2; rr++) {
            float iv = rr ? inv1 : inv0;
            int row = qb * 128 + m0 + g + rr * 8;
            uint2 v = { f2h2(o[nt][2 * rr] * iv,     o[nt][2 * rr + 1] * iv),
                        f2h2(o[nt + 1][2 * rr] * iv, o[nt + 1][2 * rr + 1] * iv) };
            g_oh[((size_t)bI * 2048 + row) * 192 + slot] = v;
        }
    }
}

// ---------------------------------------------------------------------------
extern "C" void kernel_launch(void* const* d_in, const int* in_sizes, int n_in,
                              void* d_out, int out_size)
{
    const float* x      = (const float*)d_in[0];
    const float* W_attn = (const float*)d_in[1];
    const float* b_attn = (const float*)d_in[2];
    const float* W_proj = (const float*)d_in[3];
    const float* b_proj = (const float*)d_in[4];
    float* out = (float*)d_out;

    uint2 *xh, *oh, *wah, *wph;
    cudaGetSymbolAddress((void**)&xh,  g_xh);
    cudaGetSymbolAddress((void**)&oh,  g_oh);
    cudaGetSymbolAddress((void**)&wah, g_wah);
    cudaGetSymbolAddress((void**)&wph, g_wph);

    cudaFuncSetAttribute(gemm_tc<0>, cudaFuncAttributeMaxDynamicSharedMemorySize, GEMM_SMEM);
    cudaFuncSetAttribute(gemm_tc<1>, cudaFuncAttributeMaxDynamicSharedMemorySize, GEMM_SMEM);
    cudaFuncSetAttribute(attn_tc,    cudaFuncAttributeMaxDynamicSharedMemorySize, ATT_SMEM);

    pack_a<<<MT_ * 192 / 256, 256>>>(x, xh);
    pack_b2<<<96, 256>>>(W_attn, W_proj, wah, wph);
    gemm_tc<0><<<dim3(18, 64), 128, GEMM_SMEM>>>(
        reinterpret_cast<const uint4*>(xh),
        reinterpret_cast<const uint4*>(wah), b_attn, nullptr);
    attn_tc<<<dim3(16, 48), 256, ATT_SMEM>>>();
    gemm_tc<1><<<dim3(6, 64), 128, GEMM_SMEM>>>(
        reinterpret_cast<const uint4*>(oh),
        reinterpret_cast<const uint4*>(wph), b_proj, out);
}

// round 17
// speedup vs baseline: 1.2068x; 1.2068x over previous
#include <cuda_runtime.h>
#include <cuda_fp16.h>
#include <cstdint>

#define B_  4
#define T_  2048
#define C_  768
#define H_  12
#define BH_ (B_*H_)
#define MT_ 8192

// fp16 slots, t-major per 32-k chunk: slot = chunk*8 + t*2 + ks,
// u2 = {h2(c,c+1), h2(c+8,c+9)}, c = chunk*32 + ks*16 + t*2. 192 u2 per row.
__device__ uint2 g_xh [MT_*192];     // x
__device__ uint2 g_oh [MT_*192];     // attention output (proj A)
__device__ uint2 g_wah[2304*192];    // W_attn^T slots
__device__ uint2 g_wph[768*192];     // W_proj^T slots
// fp16 attention operands
__device__ uint32_t g_q2[BH_*2048*32];
__device__ uint32_t g_k2[BH_*2048*32];
__device__ uint2    g_v2[BH_*32*64*16];

// ---------------------------------------------------------------------------
__device__ __forceinline__ uint32_t f2h2(float x, float y) {
    uint32_t r; asm("cvt.rn.f16x2.f32 %0, %1, %2;" : "=r"(r) : "f"(y), "f"(x));
    return r;
}
__device__ __forceinline__ uint32_t smem_u32(const void* p) {
    uint32_t a;
    asm("{ .reg .u64 t; cvta.to.shared.u64 t, %1; cvt.u32.u64 %0, t; }" : "=r"(a) : "l"(p));
    return a;
}
__device__ __forceinline__ void cpa16(uint32_t dst, const void* src) {
    asm volatile("cp.async.cg.shared.global [%0], [%1], 16;"
                 :: "r"(dst), "l"(__cvta_generic_to_global(src)));
}
__device__ __forceinline__ void cpa_commit() { asm volatile("cp.async.commit_group;"); }
template<int N> __device__ __forceinline__ void cpa_wait() {
    asm volatile("cp.async.wait_group %0;" :: "n"(N));
}
__device__ __forceinline__ void mma16h(float* d, const uint32_t* a, const uint32_t* b) {
    asm volatile("mma.sync.aligned.m16n8k16.row.col.f32.f16.f16.f32 "
        "{%0,%1,%2,%3}, {%4,%5,%6,%7}, {%8,%9}, {%0,%1,%2,%3};"
        : "+f"(d[0]), "+f"(d[1]), "+f"(d[2]), "+f"(d[3])
        : "r"(a[0]), "r"(a[1]), "r"(a[2]), "r"(a[3]), "r"(b[0]), "r"(b[1]));
}

// ---------------------------------------------------------------------------
// Pack kernels (t-major slot order)
// ---------------------------------------------------------------------------
__global__ __launch_bounds__(256) void pack_a(const float* __restrict__ src,
                                              uint2* __restrict__ dst)
{
    int idx = blockIdx.x * 256 + threadIdx.x;   // MT_*192
    int r = idx / 192, s = idx - r * 192;
    int chunk = s >> 3, rem = s & 7;
    int t = rem >> 1, kl = rem & 1;
    int c = chunk * 32 + kl * 16 + t * 2;
    const float* p = src + (size_t)r * C_ + c;
    dst[idx] = make_uint2(f2h2(p[0], p[1]), f2h2(p[8], p[9]));
}

// Both weight matrices in one launch: blocks [0,72) -> W_attn, [72,96) -> W_proj
__global__ __launch_bounds__(256) void pack_b2(const float* __restrict__ Wa,
                                               const float* __restrict__ Wp,
                                               uint2* __restrict__ da,
                                               uint2* __restrict__ dp)
{
    __shared__ float sw[32][33];
    int bx = blockIdx.x;
    const float* W; uint2* dst; int N;
    if (bx < 72) { W = Wa; dst = da; N = 2304; }
    else         { W = Wp; dst = dp; N = 768; bx -= 72; }
    const int n0 = bx * 32;
    const int kk = threadIdx.x >> 5, nn = threadIdx.x & 31;
    const int nl = threadIdx.x >> 3, s = threadIdx.x & 7;
    const int t = s >> 1, kl = s & 1;
    const int kb = kl * 16 + t * 2;
    for (int kc = 0; kc < 24; kc++) {
        __syncthreads();
#pragma unroll
        for (int p = 0; p < 4; p++)
            sw[kk + p * 8][nn] = W[(size_t)(kc * 32 + kk + p * 8) * N + n0 + nn];
        __syncthreads();
        dst[(size_t)(n0 + nl) * 192 + kc * 8 + s] =
            make_uint2(f2h2(sw[kb][nl], sw[kb + 1][nl]),
                       f2h2(sw[kb + 8][nl], sw[kb + 9][nl]));
    }
}

// ---------------------------------------------------------------------------
// QKV GEMM (pure fp16, paired-ks fragments) — exact R15-best configuration.
// CTA 128m x 128n, 8 warps (4m x 2n), 3-stage cp.async, dense 64B rows.
// ---------------------------------------------------------------------------
#define GSTAGE 1024
#define GEMM_SMEM 69632

__global__ __launch_bounds__(256, 2) void qkv_tc(const uint4* __restrict__ Ap,
                                                 const uint4* __restrict__ Bp,
                                                 const float* __restrict__ bias)
{
    extern __shared__ uint4 sm4[];
    const uint32_t smb = smem_u32(sm4);
    const int tid = threadIdx.x, w = tid >> 5, lane = tid & 31, g = lane >> 2, t = lane & 3;
    const int M0 = blockIdx.y * 128, N0 = blockIdx.x * 128;
    const int mw = (w & 3) * 32, nw = (w >> 2) * 64;

    const int l_row = tid >> 1, l_j = (tid & 1) * 2;
    const uint4* aBase = Ap + (size_t)(M0 + l_row) * 96 + l_j;
    const uint4* bBase = Bp + (size_t)(N0 + l_row) * 96 + l_j;
    const uint32_t dA0 = smb + (uint32_t)(l_row * 4 + l_j) * 16;
    const uint32_t dB0 = smb + (uint32_t)(512 + l_row * 4 + l_j) * 16;

    float acc[2][8][4];
#pragma unroll
    for (int mt = 0; mt < 2; mt++)
#pragma unroll
        for (int nt = 0; nt < 8; nt++)
#pragma unroll
            for (int r = 0; r < 4; r++) acc[mt][nt][r] = 0.f;

    auto issue = [&](int c, int buf) {
        uint32_t o = (uint32_t)buf * GSTAGE * 16u;
        cpa16(dA0 + o,      aBase + c * 4);
        cpa16(dA0 + o + 16, aBase + c * 4 + 1);
        cpa16(dB0 + o,      bBase + c * 4);
        cpa16(dB0 + o + 16, bBase + c * 4 + 1);
        cpa_commit();
    };

    issue(0, 0);
    issue(1, 1);

#pragma unroll 1
    for (int c3 = 0; c3 < 8; c3++) {
#pragma unroll
        for (int sub = 0; sub < 3; sub++) {
            const int c = c3 * 3 + sub;
            if (c < 23) cpa_wait<1>(); else cpa_wait<0>();
            __syncthreads();
            if (c < 22) issue(c + 2, (sub + 2) % 3);
            const uint4* sA = sm4 + sub * GSTAGE;
            const uint4* sB = sA + 512;

            uint32_t ah0[2][4], ah1[2][4];
#pragma unroll
            for (int mt = 0; mt < 2; mt++) {
                uint4 u0 = sA[(mw + mt * 16 + g) * 4 + t];
                uint4 u1 = sA[(mw + mt * 16 + g + 8) * 4 + t];
                ah0[mt][0] = u0.x; ah0[mt][1] = u1.x; ah0[mt][2] = u0.y; ah0[mt][3] = u1.y;
                ah1[mt][0] = u0.z; ah1[mt][1] = u1.z; ah1[mt][2] = u0.w; ah1[mt][3] = u1.w;
            }
#pragma unroll
            for (int grp = 0; grp < 2; grp++) {
                uint32_t b0[4][2], b1[4][2];
#pragma unroll
                for (int j = 0; j < 4; j++) {
                    uint4 ub = sB[(nw + (grp * 4 + j) * 8 + g) * 4 + t];
                    b0[j][0] = ub.x; b0[j][1] = ub.y;
                    b1[j][0] = ub.z; b1[j][1] = ub.w;
                }
#pragma unroll
                for (int j = 0; j < 4; j++) {
                    mma16h(acc[0][grp * 4 + j], ah0[0], b0[j]);
                    mma16h(acc[1][grp * 4 + j], ah0[1], b0[j]);
                }
#pragma unroll
                for (int j = 0; j < 4; j++) {
                    mma16h(acc[0][grp * 4 + j], ah1[0], b1[j]);
                    mma16h(acc[1][grp * 4 + j], ah1[1], b1[j]);
                }
            }
        }
    }

    const int which = N0 / C_;   // 128-wide tile never straddles q/k/v
    if (which < 2) {
        uint32_t* dstp = which ? g_k2 : g_q2;
        const float scl = which ? 1.f : 0.125f;
#pragma unroll
        for (int mt = 0; mt < 2; mt++)
#pragma unroll
            for (int nt = 0; nt < 8; nt++)
#pragma unroll
                for (int rr = 0; rr < 2; rr++) {
                    int m_g = M0 + mw + mt * 16 + g + rr * 8;
                    int n_g = N0 + nw + nt * 8 + 2 * t;
                    float v0 = (acc[mt][nt][2 * rr] + bias[n_g]) * scl;
                    float v1 = (acc[mt][nt][2 * rr + 1] + bias[n_g + 1]) * scl;
                    int cc = n_g - which * C_;
                    int h = cc >> 6, d = cc & 63;
                    int b = m_g >> 11, tok = m_g & 2047;
                    int idx = 8 * ((d >> 1) & 3) + 2 * (d >> 4) + ((d >> 3) & 1);
                    dstp[((size_t)(b * H_ + h) * 2048 + tok) * 32 + idx] = f2h2(v0, v1);
                }
    } else {
        __syncthreads();
        float* sv = reinterpret_cast<float*>(sm4);
#pragma unroll
        for (int mt = 0; mt < 2; mt++)
#pragma unroll
            for (int nt = 0; nt < 8; nt++)
#pragma unroll
                for (int rr = 0; rr < 2; rr++) {
                    int row = mw + mt * 16 + g + rr * 8;
                    int col = nw + nt * 8 + 2 * t;
                    sv[row * 133 + col]     = acc[mt][nt][2 * rr] + bias[N0 + col];
                    sv[row * 133 + col + 1] = acc[mt][nt][2 * rr + 1] + bias[N0 + col + 1];
                }
        __syncthreads();
        const int b = M0 >> 11, tok0 = M0 & 2047;
        const int h0 = (N0 - 2 * C_) >> 6;
#pragma unroll
        for (int r = 0; r < 16; r++) {
            int id = tid + 256 * r;            // 4096 slots: 2kb x 128c x 16
            int kb_l = id >> 11, rem = id & 2047;
            int cloc = rem >> 4, sidx = rem & 15;
            int tt = sidx >> 2, ks = sidx & 3;
            int tl0 = kb_l * 64 + ks * 16 + 2 * tt;
            float a   = sv[tl0 * 133 + cloc];
            float bb  = sv[(tl0 + 1) * 133 + cloc];
            float cfl = sv[(tl0 + 8) * 133 + cloc];
            float dfl = sv[(tl0 + 9) * 133 + cloc];
            int h = h0 + (cloc >> 6), d = cloc & 63;
            int kbg = (tok0 >> 6) + kb_l;
            g_v2[(((size_t)(b * H_ + h) * 32 + kbg) * 64 + d) * 16 + sidx] =
                make_uint2(f2h2(a, bb), f2h2(cfl, dfl));
        }
    }
}

// ---------------------------------------------------------------------------
// Proj GEMM: CTA 64m x 128n (grid 6x128 -> balanced waves), 8 warps (2m x 4n),
// warp m32n32. 3-stage cp.async, stage 768 u4 = 12KB.
// ---------------------------------------------------------------------------
#define PSTAGE 768
#define PROJ_SMEM (3*PSTAGE*16)   // 36864

__global__ __launch_bounds__(256, 2) void proj_tc(const uint4* __restrict__ Ap,
                                                  const uint4* __restrict__ Bp,
                                                  const float* __restrict__ bias,
                                                  float* __restrict__ out)
{
    extern __shared__ uint4 sm4[];
    const uint32_t smb = smem_u32(sm4);
    const int tid = threadIdx.x, w = tid >> 5, lane = tid & 31, g = lane >> 2, t = lane & 3;
    const int M0 = blockIdx.y * 64, N0 = blockIdx.x * 128;
    const int mw = (w & 1) * 32, nw = (w >> 1) * 32;

    const int a_row = tid >> 2, a_j = tid & 3;
    const int b_row = tid >> 1, b_j = (tid & 1) * 2;
    const uint4* aBase = Ap + (size_t)(M0 + a_row) * 96 + a_j;
    const uint4* bBase = Bp + (size_t)(N0 + b_row) * 96 + b_j;
    const uint32_t dA0 = smb + (uint32_t)(a_row * 4 + a_j) * 16;
    const uint32_t dB0 = smb + (uint32_t)(256 + b_row * 4 + b_j) * 16;

    float acc[2][4][4];
#pragma unroll
    for (int mt = 0; mt < 2; mt++)
#pragma unroll
        for (int nt = 0; nt < 4; nt++)
#pragma unroll
            for (int r = 0; r < 4; r++) acc[mt][nt][r] = 0.f;

    auto issue = [&](int c, int buf) {
        uint32_t o = (uint32_t)buf * PSTAGE * 16u;
        cpa16(dA0 + o,      aBase + c * 4);
        cpa16(dB0 + o,      bBase + c * 4);
        cpa16(dB0 + o + 16, bBase + c * 4 + 1);
        cpa_commit();
    };

    issue(0, 0);
    issue(1, 1);

#pragma unroll 1
    for (int c3 = 0; c3 < 8; c3++) {
#pragma unroll
        for (int sub = 0; sub < 3; sub++) {
            const int c = c3 * 3 + sub;
            if (c < 23) cpa_wait<1>(); else cpa_wait<0>();
            __syncthreads();
            if (c < 22) issue(c + 2, (sub + 2) % 3);
            const uint4* sA = sm4 + sub * PSTAGE;
            const uint4* sB = sA + 256;

            uint32_t ah0[2][4], ah1[2][4];
#pragma unroll
            for (int mt = 0; mt < 2; mt++) {
                uint4 u0 = sA[(mw + mt * 16 + g) * 4 + t];
                uint4 u1 = sA[(mw + mt * 16 + g + 8) * 4 + t];
                ah0[mt][0] = u0.x; ah0[mt][1] = u1.x; ah0[mt][2] = u0.y; ah0[mt][3] = u1.y;
                ah1[mt][0] = u0.z; ah1[mt][1] = u1.z; ah1[mt][2] = u0.w; ah1[mt][3] = u1.w;
            }
#pragma unroll
            for (int nt = 0; nt < 4; nt++) {
                uint4 ub = sB[(nw + nt * 8 + g) * 4 + t];
                uint32_t b0[2] = { ub.x, ub.y };
                uint32_t b1[2] = { ub.z, ub.w };
                mma16h(acc[0][nt], ah0[0], b0);
                mma16h(acc[1][nt], ah0[1], b0);
                mma16h(acc[0][nt], ah1[0], b1);
                mma16h(acc[1][nt], ah1[1], b1);
            }
        }
    }

#pragma unroll
    for (int mt = 0; mt < 2; mt++)
#pragma unroll
        for (int nt = 0; nt < 4; nt++)
#pragma unroll
            for (int rr = 0; rr < 2; rr++) {
                int m_g = M0 + mw + mt * 16 + g + rr * 8;
                int n_g = N0 + nw + nt * 8 + 2 * t;
                float2 v = { acc[mt][nt][2 * rr] + bias[n_g],
                             acc[mt][nt][2 * rr + 1] + bias[n_g + 1] };
                *reinterpret_cast<float2*>(out + (size_t)m_g * C_ + n_g) = v;
            }
}

// ---------------------------------------------------------------------------
// Flash attention, fp16 single-term. Q in registers; masked-tile skip;
// alpha-rescale skip. Numerically identical to R15.
// ---------------------------------------------------------------------------
#define ATT_SMEM (4608*16)

__global__ __launch_bounds__(256, 2) void attn_tc()
{
    extern __shared__ uint4 sm4[];
    const uint32_t smb = smem_u32(sm4);
    const int bh = blockIdx.y;
    const int qb = (gridDim.x - 1) - blockIdx.x;
    const int tid = threadIdx.x, w = tid >> 5, lane = tid & 31, g = lane >> 2, t = lane & 3;
    const int m0 = w * 16;

    {
        const int qr = tid >> 1, qs = (tid & 1) * 4;
        const uint4* qBase = reinterpret_cast<const uint4*>(g_q2)
                           + ((size_t)bh * 2048 + qb * 128 + qr) * 8 + qs;
        const uint32_t dQ = smb + (uint32_t)(qr * 9 + qs) * 16;
#pragma unroll
        for (int j = 0; j < 4; j++) cpa16(dQ + j * 16u, qBase + j);
    }
    const int i_n = tid >> 2, i_s = tid & 3;
    const uint4* kBase = reinterpret_cast<const uint4*>(g_k2)
                       + ((size_t)bh * 2048 + i_n) * 8 + i_s;
    const uint4* vBase = reinterpret_cast<const uint4*>(g_v2)
                       + (size_t)bh * 32 * 512 + i_n * 8 + i_s;
    const uint32_t dK0 = smb + (uint32_t)(1152 + i_n * 9 + i_s) * 16;

    auto issueKV = [&](int kb, int buf) {
        uint32_t o = (uint32_t)buf * 1152u * 16u;
        cpa16(dK0 + o,           kBase + kb * 512);
        cpa16(dK0 + o + 64,      kBase + kb * 512 + 4);
        cpa16(dK0 + o + 576u*16, vBase + kb * 512);
        cpa16(dK0 + o + 576u*16 + 64, vBase + kb * 512 + 4);
        cpa_commit();
    };

    const int nkb = 2 * qb + 2;
    issueKV(0, 0);
    issueKV(1, 1);

    const int aW = (m0 + g) * 9 + 2 * t;
    const int qr0 = qb * 128 + m0 + g;

    // Wait for group 0 (Q + KV0), then pull Q fragments into registers once.
    cpa_wait<1>();
    __syncthreads();
    uint32_t qf[4][4];
    {
        uint4 u0 = sm4[aW],     u1 = sm4[aW + 72];
        uint4 v0 = sm4[aW + 1], v1 = sm4[aW + 72 + 1];
        qf[0][0] = u0.x; qf[0][1] = u1.x; qf[0][2] = u0.y; qf[0][3] = u1.y;
        qf[1][0] = u0.z; qf[1][1] = u1.z; qf[1][2] = u0.w; qf[1][3] = u1.w;
        qf[2][0] = v0.x; qf[2][1] = v1.x; qf[2][2] = v0.y; qf[2][3] = v1.y;
        qf[3][0] = v0.z; qf[3][1] = v1.z; qf[3][2] = v0.w; qf[3][3] = v1.w;
    }

    float o[8][4];
#pragma unroll
    for (int nt = 0; nt < 8; nt++)
#pragma unroll
        for (int r = 0; r < 4; r++) o[nt][r] = 0.f;
    float mrow[2] = { -1e30f, -1e30f }, lrow[2] = { 0.f, 0.f };

    int cbuf = 0, ibuf = 2;
    for (int kb = 0; kb < nkb; kb++) {
        if (kb > 0) {
            if (kb < nkb - 1) cpa_wait<1>(); else cpa_wait<0>();
            __syncthreads();
        }
        if (kb + 2 < nkb) issueKV(kb + 2, ibuf);
        const uint4* sK = sm4 + 1152 + cbuf * 1152;
        const uint4* sV = sK + 576;

        // Warps whose rows are entirely above this k-tile: exact no-op.
        const bool active = !(kb == 2 * qb + 1 && m0 < 64);
        if (active) {

        float s[8][4];
#pragma unroll
        for (int nt = 0; nt < 8; nt++)
#pragma unroll
            for (int r = 0; r < 4; r++) s[nt][r] = 0.f;
#pragma unroll
        for (int kp = 0; kp < 2; kp++) {
#pragma unroll
            for (int grp = 0; grp < 2; grp++) {
                uint4 ub[4];
#pragma unroll
                for (int j = 0; j < 4; j++)
                    ub[j] = sK[((grp * 4 + j) * 8 + g) * 9 + 2 * t + kp];
#pragma unroll
                for (int j = 0; j < 4; j++) {
                    uint32_t b0[2] = { ub[j].x, ub[j].y };
                    mma16h(s[grp * 4 + j], qf[2 * kp], b0);
                }
#pragma unroll
                for (int j = 0; j < 4; j++) {
                    uint32_t b1[2] = { ub[j].z, ub[j].w };
                    mma16h(s[grp * 4 + j], qf[2 * kp + 1], b1);
                }
            }
        }

        if (kb >= 2 * qb) {
#pragma unroll
            for (int nt = 0; nt < 8; nt++) {
                int col = kb * 64 + nt * 8 + 2 * t;
                if (col > qr0)         s[nt][0] = -1e30f;
                if (col + 1 > qr0)     s[nt][1] = -1e30f;
                if (col > qr0 + 8)     s[nt][2] = -1e30f;
                if (col + 1 > qr0 + 8) s[nt][3] = -1e30f;
            }
        }

        float pm0 = -1e30f, pm1 = -1e30f;
#pragma unroll
        for (int nt = 0; nt < 8; nt++) {
            pm0 = fmaxf(pm0, fmaxf(s[nt][0], s[nt][1]));
            pm1 = fmaxf(pm1, fmaxf(s[nt][2], s[nt][3]));
        }
        pm0 = fmaxf(pm0, __shfl_xor_sync(0xffffffffu, pm0, 1));
        pm0 = fmaxf(pm0, __shfl_xor_sync(0xffffffffu, pm0, 2));
        pm1 = fmaxf(pm1, __shfl_xor_sync(0xffffffffu, pm1, 1));
        pm1 = fmaxf(pm1, __shfl_xor_sync(0xffffffffu, pm1, 2));
        float mn0 = fmaxf(mrow[0], pm0), mn1 = fmaxf(mrow[1], pm1);
        float al0 = __expf(mrow[0] - mn0), al1 = __expf(mrow[1] - mn1);
        bool rescale = __any_sync(0xffffffffu, (mn0 != mrow[0]) || (mn1 != mrow[1]));
        mrow[0] = mn0; mrow[1] = mn1;
        float sum0 = 0.f, sum1 = 0.f;
#pragma unroll
        for (int nt = 0; nt < 8; nt++) {
            s[nt][0] = __expf(s[nt][0] - mn0); sum0 += s[nt][0];
            s[nt][1] = __expf(s[nt][1] - mn0); sum0 += s[nt][1];
            s[nt][2] = __expf(s[nt][2] - mn1); sum1 += s[nt][2];
            s[nt][3] = __expf(s[nt][3] - mn1); sum1 += s[nt][3];
        }
        sum0 += __shfl_xor_sync(0xffffffffu, sum0, 1);
        sum0 += __shfl_xor_sync(0xffffffffu, sum0, 2);
        sum1 += __shfl_xor_sync(0xffffffffu, sum1, 1);
        sum1 += __shfl_xor_sync(0xffffffffu, sum1, 2);
        lrow[0] = lrow[0] * al0 + sum0;
        lrow[1] = lrow[1] * al1 + sum1;
        if (rescale) {
#pragma unroll
            for (int nt = 0; nt < 8; nt++) {
                o[nt][0] *= al0; o[nt][1] *= al0;
                o[nt][2] *= al1; o[nt][3] *= al1;
            }
        }

#pragma unroll
        for (int kp = 0; kp < 2; kp++) {
#pragma unroll
            for (int grp = 0; grp < 2; grp++) {
                uint4 ub[4];
#pragma unroll
                for (int j = 0; j < 4; j++)
                    ub[j] = sV[((grp * 4 + j) * 8 + g) * 9 + 2 * t + kp];
#pragma unroll
                for (int half = 0; half < 2; half++) {
                    const int ks = 2 * kp + half;
                    uint32_t pa[4] = {
                        f2h2(s[2 * ks][0],     s[2 * ks][1]),
                        f2h2(s[2 * ks][2],     s[2 * ks][3]),
                        f2h2(s[2 * ks + 1][0], s[2 * ks + 1][1]),
                        f2h2(s[2 * ks + 1][2], s[2 * ks + 1][3]) };
#pragma unroll
                    for (int j = 0; j < 4; j++) {
                        uint32_t bv[2] = { half ? ub[j].z : ub[j].x,
                                           half ? ub[j].w : ub[j].y };
                        mma16h(o[grp * 4 + j], pa, bv);
                    }
                }
            }
        }

        }   // active

        cbuf = (cbuf == 2) ? 0 : cbuf + 1;
        ibuf = (ibuf == 2) ? 0 : ibuf + 1;
    }

    // epilogue: normalize, write fp16 A-slots for proj (t-major chunk order)
    float inv0 = 1.f / lrow[0], inv1 = 1.f / lrow[1];
    const int bI = bh / H_, hI = bh - bI * H_;
#pragma unroll
    for (int np = 0; np < 4; np++) {
        const int nt = np * 2;
        const int K16 = hI * 4 + np;
        const int slot = (K16 >> 1) * 8 + t * 2 + (K16 & 1);
#pragma unroll
        for (int rr = 0; rr < 2; rr++) {
            float iv = rr ? inv1 : inv0;
            int row = qb * 128 + m0 + g + rr * 8;
            uint2 v = { f2h2(o[nt][2 * rr] * iv,     o[nt][2 * rr + 1] * iv),
                        f2h2(o[nt + 1][2 * rr] * iv, o[nt + 1][2 * rr + 1] * iv) };
            g_oh[((size_t)bI * 2048 + row) * 192 + slot] = v;
        }
    }
}

// ---------------------------------------------------------------------------
extern "C" void kernel_launch(void* const* d_in, const int* in_sizes, int n_in,
                              void* d_out, int out_size)
{
    const float* x      = (const float*)d_in[0];
    const float* W_attn = (const float*)d_in[1];
    const float* b_attn = (const float*)d_in[2];
    const float* W_proj = (const float*)d_in[3];
    const float* b_proj = (const float*)d_in[4];
    float* out = (float*)d_out;

    uint2 *xh, *oh, *wah, *wph;
    cudaGetSymbolAddress((void**)&xh,  g_xh);
    cudaGetSymbolAddress((void**)&oh,  g_oh);
    cudaGetSymbolAddress((void**)&wah, g_wah);
    cudaGetSymbolAddress((void**)&wph, g_wph);

    cudaFuncSetAttribute(qkv_tc,  cudaFuncAttributeMaxDynamicSharedMemorySize, GEMM_SMEM);
    cudaFuncSetAttribute(proj_tc, cudaFuncAttributeMaxDynamicSharedMemorySize, PROJ_SMEM);
    cudaFuncSetAttribute(attn_tc, cudaFuncAttributeMaxDynamicSharedMemorySize, ATT_SMEM);

    pack_a<<<MT_ * 192 / 256, 256>>>(x, xh);
    pack_b2<<<96, 256>>>(W_attn, W_proj, wah, wph);
    qkv_tc<<<dim3(18, 64), 256, GEMM_SMEM>>>(
        reinterpret_cast<const uint4*>(xh),
        reinterpret_cast<const uint4*>(wah), b_attn);
    attn_tc<<<dim3(16, 48), 256, ATT_SMEM>>>();
    proj_tc<<<dim3(6, 128), 256, PROJ_SMEM>>>(
        reinterpret_cast<const uint4*>(oh),
        reinterpret_cast<const uint4*>(wph), b_proj, out);
}